// round 1
// baseline (speedup 1.0000x reference)
#include <cuda_runtime.h>

// SoftQuantize: x (8192,512) fp32, c (4,256) fp32, sigma (1,) fp32 -> out (8192,512) fp32
// rows = 8192*128 = 1,048,576 subvectors of dim 4; softmax over 256 centers.
//
// arg_l = k1 * (z . c_l) + beta_l, k1 = 2*s*log2e, beta_l = -s*log2e*||c_l||^2
// (z_sq term dropped: constant per row, softmax shift-invariant)
// out = (sum_l 2^(arg_l - m) * c_l) / (sum_l 2^(arg_l - m)); c pre-scaled by k1,
// un-scaled by 1/k1 at the end (cancels in denominator).

#define LQ 256
#define TPB 256
#define G 4
#define NROWS (8192*128)

typedef unsigned long long u64;

static __device__ __forceinline__ u64 pk(float lo, float hi) {
    u64 r; asm("mov.b64 %0, {%1, %2};" : "=l"(r) : "f"(lo), "f"(hi)); return r;
}
static __device__ __forceinline__ void unpk(u64 v, float& lo, float& hi) {
    asm("mov.b64 {%0, %1}, %2;" : "=f"(lo), "=f"(hi) : "l"(v));
}
// sm_103a packed fp32x2 FMA (2x fp32 FMA throughput vs scalar FFMA-3reg)
static __device__ __forceinline__ u64 f2fma(u64 a, u64 b, u64 c) {
    u64 d; asm("fma.rn.f32x2 %0, %1, %2, %3;" : "=l"(d) : "l"(a), "l"(b), "l"(c)); return d;
}
static __device__ __forceinline__ float ex2f(float x) {
    float y; asm("ex2.approx.f32 %0, %1;" : "=f"(y) : "f"(x)); return y;
}
static __device__ __forceinline__ float rcpf(float x) {
    float y; asm("rcp.approx.f32 %0, %1;" : "=f"(y) : "f"(x)); return y;
}

__global__ __launch_bounds__(TPB)
void softq_kernel(const float4* __restrict__ x4,
                  const float*  __restrict__ c,
                  const float*  __restrict__ sigma,
                  float4*       __restrict__ out4)
{
    __shared__ ulonglong2 sc[LQ];   // {k1*c0,k1*c1},{k1*c2,k1*c3} per center
    __shared__ float      sb[LQ];   // beta_l

    const float LOG2E = 1.4426950408889634f;
    float s  = fmaxf(sigma[0], 0.0f) + 1e-4f;
    float k1 = 2.0f * s * LOG2E;

    int t = threadIdx.x;  // t == l for codebook setup (TPB == LQ)
    {
        float c0 = c[t], c1 = c[LQ + t], c2 = c[2*LQ + t], c3 = c[3*LQ + t];
        float csq = c0*c0 + c1*c1 + c2*c2 + c3*c3;
        sc[t].x = pk(k1*c0, k1*c1);
        sc[t].y = pk(k1*c2, k1*c3);
        sb[t]   = -s * LOG2E * csq;
    }
    __syncthreads();

    const int base = blockIdx.x * (TPB * G) + t;   // row indices: base + g*TPB

    u64 z01[G], z23[G];
    #pragma unroll
    for (int g = 0; g < G; ++g) {
        float4 z = x4[base + g*TPB];
        z01[g] = pk(z.x, z.y);
        z23[g] = pk(z.z, z.w);
    }

    // ---- pass A: exact row max of arg ----
    float m[G];
    #pragma unroll
    for (int g = 0; g < G; ++g) m[g] = -3.4e38f;

    #pragma unroll 4
    for (int l = 0; l < LQ; ++l) {
        ulonglong2 cp = sc[l];
        u64 b0 = pk(sb[l], 0.0f);
        #pragma unroll
        for (int g = 0; g < G; ++g) {
            u64 d = f2fma(z01[g], cp.x, b0);
            d     = f2fma(z23[g], cp.y, d);
            float a, b2; unpk(d, a, b2);
            m[g] = fmaxf(m[g], a + b2);
        }
    }

    // ---- pass B: exp + accumulate numerator (packed) and denominator ----
    float negm[G], den[G];
    u64 n01[G], n23[G];
    #pragma unroll
    for (int g = 0; g < G; ++g) { negm[g] = -m[g]; den[g] = 0.0f; n01[g] = 0ull; n23[g] = 0ull; }

    #pragma unroll 4
    for (int l = 0; l < LQ; ++l) {
        ulonglong2 cp = sc[l];
        u64 b0 = pk(sb[l], 0.0f);
        #pragma unroll
        for (int g = 0; g < G; ++g) {
            u64 d = f2fma(z01[g], cp.x, b0);
            d     = f2fma(z23[g], cp.y, d);
            float a, b2; unpk(d, a, b2);
            float p = ex2f((a + b2) + negm[g]);   // in (0,1], max term == 1
            den[g] += p;
            u64 pp = pk(p, p);
            n01[g] = f2fma(pp, cp.x, n01[g]);
            n23[g] = f2fma(pp, cp.y, n23[g]);
        }
    }

    // ---- epilogue: divide, undo k1 scaling of c ----
    float invk1 = 1.0f / k1;
    #pragma unroll
    for (int g = 0; g < G; ++g) {
        float sf = rcpf(den[g]) * invk1;          // den >= 1 always
        float a, b2, cc, dd;
        unpk(n01[g], a, b2);
        unpk(n23[g], cc, dd);
        out4[base + g*TPB] = make_float4(a*sf, b2*sf, cc*sf, dd*sf);
    }
}

extern "C" void kernel_launch(void* const* d_in, const int* in_sizes, int n_in,
                              void* d_out, int out_size)
{
    const float* x     = (const float*)d_in[0];
    const float* c     = (const float*)d_in[1];
    const float* sigma = (const float*)d_in[2];
    float* out = (float*)d_out;

    int blocks = NROWS / (TPB * G);   // 1024
    softq_kernel<<<blocks, TPB>>>((const float4*)x, c, sigma, (float4*)out);
}

// round 2
// speedup vs baseline: 1.1619x; 1.1619x over previous
#include <cuda_runtime.h>

// SoftQuantize: x (8192,512) fp32, c (4,256) fp32, sigma (1,) fp32 -> out (8192,512) fp32
// rows = 8192*128 subvectors of dim 4; softmax over 256 centers.
//
// Row-pair packing: f32x2 lanes hold the SAME component of TWO rows, centers are
// broadcast-packed pk(c_m, c_m). Each f32x2 half is then a complete per-row value:
// no horizontal adds, and denominator/numerators accumulate packed across the pair.
//
// arg_l = k1*(z.c_l) + beta_l, k1 = 2*s*log2e, beta_l = -s*log2e*||c_l||^2
// (z_sq dropped: softmax shift-invariant). c pre-scaled by k1, undone at the end.

#define LQ 256
#define TPB 256
#define G 4                 // rows per thread = 2 pairs
#define NROWS (8192*128)

typedef unsigned long long u64;

static __device__ __forceinline__ u64 pk(float lo, float hi) {
    u64 r; asm("mov.b64 %0, {%1, %2};" : "=l"(r) : "f"(lo), "f"(hi)); return r;
}
static __device__ __forceinline__ void unpk(u64 v, float& lo, float& hi) {
    asm("mov.b64 {%0, %1}, %2;" : "=f"(lo), "=f"(hi) : "l"(v));
}
static __device__ __forceinline__ u64 f2fma(u64 a, u64 b, u64 c) {
    u64 d; asm("fma.rn.f32x2 %0, %1, %2, %3;" : "=l"(d) : "l"(a), "l"(b), "l"(c)); return d;
}
static __device__ __forceinline__ u64 f2add(u64 a, u64 b) {
    u64 d; asm("add.rn.f32x2 %0, %1, %2;" : "=l"(d) : "l"(a), "l"(b)); return d;
}
static __device__ __forceinline__ float ex2f(float x) {
    float y; asm("ex2.approx.f32 %0, %1;" : "=f"(y) : "f"(x)); return y;
}
static __device__ __forceinline__ float rcpf(float x) {
    float y; asm("rcp.approx.f32 %0, %1;" : "=f"(y) : "f"(x)); return y;
}

__global__ __launch_bounds__(TPB)
void softq_kernel(const float4* __restrict__ x4,
                  const float*  __restrict__ c,
                  const float*  __restrict__ sigma,
                  float4*       __restrict__ out4)
{
    __shared__ ulonglong2 scA[LQ];  // { pk(k1*c0,k1*c0), pk(k1*c1,k1*c1) }
    __shared__ ulonglong2 scB[LQ];  // { pk(k1*c2,k1*c2), pk(k1*c3,k1*c3) }
    __shared__ u64        sbb[LQ];  // pk(beta, beta)

    const float LOG2E = 1.4426950408889634f;
    float s  = fmaxf(sigma[0], 0.0f) + 1e-4f;
    float k1 = 2.0f * s * LOG2E;

    int t = threadIdx.x;            // t == center index for setup (TPB == LQ)
    {
        float c0 = c[t], c1 = c[LQ + t], c2 = c[2*LQ + t], c3 = c[3*LQ + t];
        float csq  = c0*c0 + c1*c1 + c2*c2 + c3*c3;
        float beta = -s * LOG2E * csq;
        scA[t].x = pk(k1*c0, k1*c0);
        scA[t].y = pk(k1*c1, k1*c1);
        scB[t].x = pk(k1*c2, k1*c2);
        scB[t].y = pk(k1*c3, k1*c3);
        sbb[t]   = pk(beta, beta);
    }
    __syncthreads();

    const int base = blockIdx.x * (TPB * G) + t;  // rows: base + g*TPB, g=0..3

    // zz[m][p]: component m of rows (2p, 2p+1) packed
    u64 zz[4][2];
    #pragma unroll
    for (int p = 0; p < 2; ++p) {
        float4 a = x4[base + (2*p    ) * TPB];
        float4 b = x4[base + (2*p + 1) * TPB];
        zz[0][p] = pk(a.x, b.x);
        zz[1][p] = pk(a.y, b.y);
        zz[2][p] = pk(a.z, b.z);
        zz[3][p] = pk(a.w, b.w);
    }

    // ---- pass A: exact per-row max of arg ----
    float mLo[2] = {-3.4e38f, -3.4e38f};
    float mHi[2] = {-3.4e38f, -3.4e38f};

    #pragma unroll 4
    for (int l = 0; l < LQ; ++l) {
        ulonglong2 cA = scA[l];
        ulonglong2 cB = scB[l];
        u64 bb = sbb[l];
        #pragma unroll
        for (int p = 0; p < 2; ++p) {
            u64 d = f2fma(zz[0][p], cA.x, bb);
            d     = f2fma(zz[1][p], cA.y, d);
            d     = f2fma(zz[2][p], cB.x, d);
            d     = f2fma(zz[3][p], cB.y, d);
            float lo, hi; unpk(d, lo, hi);
            mLo[p] = fmaxf(mLo[p], lo);
            mHi[p] = fmaxf(mHi[p], hi);
        }
    }

    // ---- pass B: exp + packed accumulation ----
    u64 negm[2], den2[2], nn[4][2];
    #pragma unroll
    for (int p = 0; p < 2; ++p) {
        negm[p] = pk(-mLo[p], -mHi[p]);
        den2[p] = 0ull;
        nn[0][p] = nn[1][p] = nn[2][p] = nn[3][p] = 0ull;
    }

    #pragma unroll 4
    for (int l = 0; l < LQ; ++l) {
        ulonglong2 cA = scA[l];
        ulonglong2 cB = scB[l];
        u64 bb = sbb[l];
        #pragma unroll
        for (int p = 0; p < 2; ++p) {
            u64 d = f2fma(zz[0][p], cA.x, bb);
            d     = f2fma(zz[1][p], cA.y, d);
            d     = f2fma(zz[2][p], cB.x, d);
            d     = f2fma(zz[3][p], cB.y, d);
            u64 a2 = f2add(d, negm[p]);
            float aLo, aHi; unpk(a2, aLo, aHi);
            float pLo = ex2f(aLo);           // in (0,1], max term == 1
            float pHi = ex2f(aHi);
            u64 pp = pk(pLo, pHi);
            den2[p]  = f2add(den2[p], pp);
            nn[0][p] = f2fma(pp, cA.x, nn[0][p]);
            nn[1][p] = f2fma(pp, cA.y, nn[1][p]);
            nn[2][p] = f2fma(pp, cB.x, nn[2][p]);
            nn[3][p] = f2fma(pp, cB.y, nn[3][p]);
        }
    }

    // ---- epilogue: divide, undo k1 scaling of c ----
    float invk1 = 1.0f / k1;
    #pragma unroll
    for (int p = 0; p < 2; ++p) {
        float dLo, dHi; unpk(den2[p], dLo, dHi);
        float sfLo = rcpf(dLo) * invk1;      // den >= 1 always
        float sfHi = rcpf(dHi) * invk1;
        float n0l, n0h, n1l, n1h, n2l, n2h, n3l, n3h;
        unpk(nn[0][p], n0l, n0h);
        unpk(nn[1][p], n1l, n1h);
        unpk(nn[2][p], n2l, n2h);
        unpk(nn[3][p], n3l, n3h);
        out4[base + (2*p    ) * TPB] = make_float4(n0l*sfLo, n1l*sfLo, n2l*sfLo, n3l*sfLo);
        out4[base + (2*p + 1) * TPB] = make_float4(n0h*sfHi, n1h*sfHi, n2h*sfHi, n3h*sfHi);
    }
}

extern "C" void kernel_launch(void* const* d_in, const int* in_sizes, int n_in,
                              void* d_out, int out_size)
{
    const float* x     = (const float*)d_in[0];
    const float* c     = (const float*)d_in[1];
    const float* sigma = (const float*)d_in[2];
    float* out = (float*)d_out;

    int blocks = NROWS / (TPB * G);   // 1024
    softq_kernel<<<blocks, TPB>>>((const float4*)x, c, sigma, (float4*)out);
}

// round 4
// speedup vs baseline: 1.2407x; 1.0678x over previous
#include <cuda_runtime.h>

// SoftQuantize: x (8192,512) fp32, c (4,256) fp32, sigma (1,) fp32 -> out (8192,512) fp32
// rows = 8192*128 subvectors of dim 4; softmax over 256 centers.
//
// Exact ONLINE (flash) softmax, tiled by T=8 centers: each dot product is
// computed exactly once, cached in registers for the tile, then exp'd against
// the running max (rescaling accumulators by 2^(Mold-Mnew) once per tile).
// Row-pair f32x2 packing throughout: each half-lane is a complete per-row value.
//
// arg_l = k1*(z.c_l) + beta_l, k1 = 2*s*log2e, beta_l = -s*log2e*||c_l||^2
// (z_sq dropped: softmax shift-invariant; running max makes this safe).
// c pre-scaled by k1 (cancels in the ratio; undone by 1/k1 at the end).

#define LQ 256
#define TPB 256
#define G 4                 // rows per thread = 2 pairs
#define TT 8                // center tile size
#define NROWS (8192*128)

typedef unsigned long long u64;

static __device__ __forceinline__ u64 pk(float lo, float hi) {
    u64 r; asm("mov.b64 %0, {%1, %2};" : "=l"(r) : "f"(lo), "f"(hi)); return r;
}
static __device__ __forceinline__ void unpk(u64 v, float& lo, float& hi) {
    asm("mov.b64 {%0, %1}, %2;" : "=f"(lo), "=f"(hi) : "l"(v));
}
static __device__ __forceinline__ u64 f2fma(u64 a, u64 b, u64 c) {
    u64 d; asm("fma.rn.f32x2 %0, %1, %2, %3;" : "=l"(d) : "l"(a), "l"(b), "l"(c)); return d;
}
static __device__ __forceinline__ u64 f2add(u64 a, u64 b) {
    u64 d; asm("add.rn.f32x2 %0, %1, %2;" : "=l"(d) : "l"(a), "l"(b)); return d;
}
static __device__ __forceinline__ u64 f2mul(u64 a, u64 b) {
    u64 d; asm("mul.rn.f32x2 %0, %1, %2;" : "=l"(d) : "l"(a), "l"(b)); return d;
}
static __device__ __forceinline__ float ex2f(float x) {
    float y; asm("ex2.approx.f32 %0, %1;" : "=f"(y) : "f"(x)); return y;
}
static __device__ __forceinline__ float rcpf(float x) {
    float y; asm("rcp.approx.f32 %0, %1;" : "=f"(y) : "f"(x)); return y;
}

__global__ __launch_bounds__(TPB, 2)
void softq_kernel(const float4* __restrict__ x4,
                  const float*  __restrict__ c,
                  const float*  __restrict__ sigma,
                  float4*       __restrict__ out4)
{
    __shared__ ulonglong2 scA[LQ];  // { pk(k1*c0,k1*c0), pk(k1*c1,k1*c1) }
    __shared__ ulonglong2 scB[LQ];  // { pk(k1*c2,k1*c2), pk(k1*c3,k1*c3) }
    __shared__ u64        sbb[LQ];  // pk(beta, beta)

    const float LOG2E = 1.4426950408889634f;
    float s  = fmaxf(sigma[0], 0.0f) + 1e-4f;
    float k1 = 2.0f * s * LOG2E;

    int t = threadIdx.x;            // t == center index for setup (TPB == LQ)
    {
        float c0 = c[t], c1 = c[LQ + t], c2 = c[2*LQ + t], c3 = c[3*LQ + t];
        float csq  = c0*c0 + c1*c1 + c2*c2 + c3*c3;
        float beta = -s * LOG2E * csq;
        scA[t].x = pk(k1*c0, k1*c0);
        scA[t].y = pk(k1*c1, k1*c1);
        scB[t].x = pk(k1*c2, k1*c2);
        scB[t].y = pk(k1*c3, k1*c3);
        sbb[t]   = pk(beta, beta);
    }
    __syncthreads();

    const int base = blockIdx.x * (TPB * G) + t;  // rows: base + g*TPB, g=0..3

    // zz[m][p]: component m of rows (2p, 2p+1) packed
    u64 zz[4][2];
    #pragma unroll
    for (int p = 0; p < 2; ++p) {
        float4 a = x4[base + (2*p    ) * TPB];
        float4 b = x4[base + (2*p + 1) * TPB];
        zz[0][p] = pk(a.x, b.x);
        zz[1][p] = pk(a.y, b.y);
        zz[2][p] = pk(a.z, b.z);
        zz[3][p] = pk(a.w, b.w);
    }

    // running max (scalar halves), its packed negation, accumulators
    float mLo[2] = {-1.0e30f, -1.0e30f};
    float mHi[2] = {-1.0e30f, -1.0e30f};
    u64 negM[2]  = {0ull, 0ull};          // set per tile before use
    u64 den2[2]  = {0ull, 0ull};
    u64 nn[4][2];
    nn[0][0] = nn[1][0] = nn[2][0] = nn[3][0] = 0ull;
    nn[0][1] = nn[1][1] = nn[2][1] = nn[3][1] = 0ull;

    #pragma unroll 1
    for (int tile = 0; tile < LQ; tile += TT) {
        // ---- phase 1: dots for the tile (cached) + scalar max tracking ----
        u64 aa[TT][2];
        float tLo[2] = {-1.0e30f, -1.0e30f};
        float tHi[2] = {-1.0e30f, -1.0e30f};
        #pragma unroll
        for (int i = 0; i < TT; ++i) {
            int l = tile + i;
            ulonglong2 cA = scA[l];
            ulonglong2 cB = scB[l];
            u64 bb = sbb[l];
            #pragma unroll
            for (int p = 0; p < 2; ++p) {
                u64 d = f2fma(zz[0][p], cA.x, bb);
                d     = f2fma(zz[1][p], cA.y, d);
                d     = f2fma(zz[2][p], cB.x, d);
                d     = f2fma(zz[3][p], cB.y, d);
                aa[i][p] = d;
                float lo, hi; unpk(d, lo, hi);
                tLo[p] = fmaxf(tLo[p], lo);
                tHi[p] = fmaxf(tHi[p], hi);
            }
        }

        // ---- running-max update + accumulator rescale (once per tile) ----
        #pragma unroll
        for (int p = 0; p < 2; ++p) {
            float nmLo = fmaxf(mLo[p], tLo[p]);
            float nmHi = fmaxf(mHi[p], tHi[p]);
            float rLo = ex2f(mLo[p] - nmLo);   // <= 1; 0 on first tile
            float rHi = ex2f(mHi[p] - nmHi);
            mLo[p] = nmLo; mHi[p] = nmHi;
            negM[p] = pk(-nmLo, -nmHi);
            u64 rr = pk(rLo, rHi);
            den2[p]  = f2mul(den2[p], rr);
            nn[0][p] = f2mul(nn[0][p], rr);
            nn[1][p] = f2mul(nn[1][p], rr);
            nn[2][p] = f2mul(nn[2][p], rr);
            nn[3][p] = f2mul(nn[3][p], rr);
        }

        // ---- phase 2: exp from cached args + packed accumulation ----
        #pragma unroll
        for (int i = 0; i < TT; ++i) {
            int l = tile + i;
            ulonglong2 cA = scA[l];
            ulonglong2 cB = scB[l];
            #pragma unroll
            for (int p = 0; p < 2; ++p) {
                u64 sa = f2add(aa[i][p], negM[p]);   // arg - M <= 0
                float aL, aH; unpk(sa, aL, aH);
                u64 pp = pk(ex2f(aL), ex2f(aH));
                den2[p]  = f2add(den2[p], pp);
                nn[0][p] = f2fma(pp, cA.x, nn[0][p]);
                nn[1][p] = f2fma(pp, cA.y, nn[1][p]);
                nn[2][p] = f2fma(pp, cB.x, nn[2][p]);
                nn[3][p] = f2fma(pp, cB.y, nn[3][p]);
            }
        }
    }

    // ---- epilogue: divide, undo k1 scaling of c ----
    float invk1 = 1.0f / k1;
    #pragma unroll
    for (int p = 0; p < 2; ++p) {
        float dLo, dHi; unpk(den2[p], dLo, dHi);
        float sfLo = rcpf(dLo) * invk1;      // den >= 1 (max term == 1)
        float sfHi = rcpf(dHi) * invk1;
        float n0l, n0h, n1l, n1h, n2l, n2h, n3l, n3h;
        unpk(nn[0][p], n0l, n0h);
        unpk(nn[1][p], n1l, n1h);
        unpk(nn[2][p], n2l, n2h);
        unpk(nn[3][p], n3l, n3h);
        out4[base + (2*p    ) * TPB] = make_float4(n0l*sfLo, n1l*sfLo, n2l*sfLo, n3l*sfLo);
        out4[base + (2*p + 1) * TPB] = make_float4(n0h*sfHi, n1h*sfHi, n2h*sfHi, n3h*sfHi);
    }
}

extern "C" void kernel_launch(void* const* d_in, const int* in_sizes, int n_in,
                              void* d_out, int out_size)
{
    const float* x     = (const float*)d_in[0];
    const float* c     = (const float*)d_in[1];
    const float* sigma = (const float*)d_in[2];
    float* out = (float*)d_out;

    int blocks = NROWS / (TPB * G);   // 1024
    softq_kernel<<<blocks, TPB>>>((const float4*)x, c, sigma, (float4*)out);
}